// round 1
// baseline (speedup 1.0000x reference)
#include <cuda_runtime.h>
#include <cuda_bf16.h>
#include <math.h>

#define S_LEN 4096
#define DIM   128
#define BQ    128
#define BK    128
#define NTHREADS 256
#define NEG (-1000000000.0f)

// XOR swizzle on float4 index: rows differing by 8 land in different bank groups.
__device__ __forceinline__ int f4sw(int r, int f4) { return f4 ^ ((r >> 3) & 7); }

__global__ __launch_bounds__(NTHREADS, 1)
void swa_kernel(const float* __restrict__ gq, const float* __restrict__ gk,
                const float* __restrict__ gv, const int* __restrict__ wptr,
                float* __restrict__ gout)
{
    extern __shared__ float sm[];
    float* sQ  = sm;                 // [128][128] swizzled
    float* sKV = sm + BQ * DIM;      // K tile, then reused for V tile
    float* sP  = sm + 2 * BQ * DIM;  // probabilities

    const int tid = threadIdx.x;
    const int ty  = tid >> 4;        // 0..15 -> rows ty*8..ty*8+7
    const int tx  = tid & 15;        // 0..15 -> cols tx*8..tx*8+7
    const int q0  = blockIdx.x * BQ;
    const int b   = blockIdx.y;
    const int w   = *wptr;

    // ---- load Q tile (pre-scaled by 1/sqrt(D)) ----
    {
        const float scale = rsqrtf((float)DIM);
        const float4* qg = reinterpret_cast<const float4*>(gq + ((size_t)b * S_LEN + q0) * DIM);
        #pragma unroll
        for (int it = 0; it < (BQ * DIM / 4) / NTHREADS; it++) {
            int idx = tid + it * NTHREADS;
            int r = idx >> 5, f4 = idx & 31;
            float4 val = qg[idx];
            val.x *= scale; val.y *= scale; val.z *= scale; val.w *= scale;
            reinterpret_cast<float4*>(sQ + r * DIM)[f4sw(r, f4)] = val;
        }
    }

    float acc[8][8];
    float m_i[8], l_i[8];
    #pragma unroll
    for (int i = 0; i < 8; i++) {
        m_i[i] = -INFINITY; l_i[i] = 0.f;
        #pragma unroll
        for (int j = 0; j < 8; j++) acc[i][j] = 0.f;
    }

    int lo = q0 - (w - 1);            if (lo < 0) lo = 0;
    int hi = q0 + BQ - 1 + (w - 1);   if (hi > S_LEN - 1) hi = S_LEN - 1;

    const int keyA = ty & 7;
    const int keyB = tx & 7;

    for (int k0 = (lo & ~(BK - 1)); k0 <= hi; k0 += BK) {
        __syncthreads();   // prior PV done reading sKV (no-op first iter)

        // ---- load K tile ----
        {
            const float4* kg = reinterpret_cast<const float4*>(gk + ((size_t)b * S_LEN + k0) * DIM);
            #pragma unroll
            for (int it = 0; it < (BK * DIM / 4) / NTHREADS; it++) {
                int idx = tid + it * NTHREADS;
                int r = idx >> 5, f4 = idx & 31;
                reinterpret_cast<float4*>(sKV + r * DIM)[f4sw(r, f4)] = kg[idx];
            }
        }
        __syncthreads();   // Q + K visible

        // ---- S = Q K^T : 8x8 micro-tile per thread ----
        float c[8][8];
        #pragma unroll
        for (int i = 0; i < 8; i++)
            #pragma unroll
            for (int j = 0; j < 8; j++) c[i][j] = 0.f;

        #pragma unroll 2
        for (int d4 = 0; d4 < DIM / 4; d4++) {
            float4 a4[8];
            #pragma unroll
            for (int i = 0; i < 8; i++)
                a4[i] = reinterpret_cast<const float4*>(sQ + (ty * 8 + i) * DIM)[d4 ^ keyA];
            #pragma unroll
            for (int jh = 0; jh < 2; jh++) {
                float4 b4[4];
                #pragma unroll
                for (int j = 0; j < 4; j++)
                    b4[j] = reinterpret_cast<const float4*>(sKV + (tx * 8 + jh * 4 + j) * DIM)[d4 ^ keyB];
                #pragma unroll
                for (int i = 0; i < 8; i++)
                    #pragma unroll
                    for (int j = 0; j < 4; j++) {
                        c[i][jh * 4 + j] += a4[i].x * b4[j].x;
                        c[i][jh * 4 + j] += a4[i].y * b4[j].y;
                        c[i][jh * 4 + j] += a4[i].z * b4[j].z;
                        c[i][jh * 4 + j] += a4[i].w * b4[j].w;
                    }
            }
        }

        // ---- band mask + online softmax (registers + shfl over 16-lane row group) ----
        #pragma unroll
        for (int i = 0; i < 8; i++) {
            const int gi = q0 + ty * 8 + i;
            #pragma unroll
            for (int j = 0; j < 8; j++) {
                const int gj = k0 + tx * 8 + j;
                const int dd = gi - gj;
                if (dd >= w || -dd >= w) c[i][j] = NEG;
            }
            float mx = c[i][0];
            #pragma unroll
            for (int j = 1; j < 8; j++) mx = fmaxf(mx, c[i][j]);
            #pragma unroll
            for (int off = 8; off; off >>= 1)
                mx = fmaxf(mx, __shfl_xor_sync(0xffffffffu, mx, off, 16));

            const float mnew = fmaxf(m_i[i], mx);
            const float corr = __expf(m_i[i] - mnew);
            float sum = 0.f;
            #pragma unroll
            for (int j = 0; j < 8; j++) {
                float p = __expf(c[i][j] - mnew);
                c[i][j] = p;
                sum += p;
            }
            #pragma unroll
            for (int off = 8; off; off >>= 1)
                sum += __shfl_xor_sync(0xffffffffu, sum, off, 16);

            m_i[i] = mnew;
            l_i[i] = l_i[i] * corr + sum;
            #pragma unroll
            for (int j = 0; j < 8; j++) acc[i][j] *= corr;
        }

        __syncthreads();   // everyone done reading K before V overwrites sKV

        // ---- store P to smem, load V tile into sKV ----
        #pragma unroll
        for (int i = 0; i < 8; i++) {
            int r = ty * 8 + i;
            float4 p0 = make_float4(c[i][0], c[i][1], c[i][2], c[i][3]);
            float4 p1 = make_float4(c[i][4], c[i][5], c[i][6], c[i][7]);
            reinterpret_cast<float4*>(sP + r * DIM)[f4sw(r, tx * 2)]     = p0;
            reinterpret_cast<float4*>(sP + r * DIM)[f4sw(r, tx * 2 + 1)] = p1;
        }
        {
            const float4* vg = reinterpret_cast<const float4*>(gv + ((size_t)b * S_LEN + k0) * DIM);
            #pragma unroll
            for (int it = 0; it < (BK * DIM / 4) / NTHREADS; it++) {
                int idx = tid + it * NTHREADS;
                int r = idx >> 5, f4 = idx & 31;
                reinterpret_cast<float4*>(sKV + r * DIM)[f4sw(r, f4)] = vg[idx];
            }
        }
        __syncthreads();   // P + V visible

        // ---- O += P V : 8 rows x 8 cols per thread ----
        #pragma unroll 2
        for (int kk = 0; kk < BK; kk++) {
            const int pidx = (((kk >> 2) ^ keyA) << 2) | (kk & 3);
            float pv[8];
            #pragma unroll
            for (int i = 0; i < 8; i++)
                pv[i] = sP[(ty * 8 + i) * DIM + pidx];
            const int keyV = (kk >> 3) & 7;
            const float4 v0 = reinterpret_cast<const float4*>(sKV + kk * DIM)[(tx * 2) ^ keyV];
            const float4 v1 = reinterpret_cast<const float4*>(sKV + kk * DIM)[(tx * 2 + 1) ^ keyV];
            #pragma unroll
            for (int i = 0; i < 8; i++) {
                acc[i][0] += pv[i] * v0.x;  acc[i][1] += pv[i] * v0.y;
                acc[i][2] += pv[i] * v0.z;  acc[i][3] += pv[i] * v0.w;
                acc[i][4] += pv[i] * v1.x;  acc[i][5] += pv[i] * v1.y;
                acc[i][6] += pv[i] * v1.z;  acc[i][7] += pv[i] * v1.w;
            }
        }
    }

    // ---- normalize + store ----
    float4* og = reinterpret_cast<float4*>(gout + ((size_t)b * S_LEN + q0) * DIM);
    #pragma unroll
    for (int i = 0; i < 8; i++) {
        const float inv = 1.0f / l_i[i];
        float4 o0 = make_float4(acc[i][0] * inv, acc[i][1] * inv, acc[i][2] * inv, acc[i][3] * inv);
        float4 o1 = make_float4(acc[i][4] * inv, acc[i][5] * inv, acc[i][6] * inv, acc[i][7] * inv);
        og[(ty * 8 + i) * (DIM / 4) + tx * 2]     = o0;
        og[(ty * 8 + i) * (DIM / 4) + tx * 2 + 1] = o1;
    }
}

extern "C" void kernel_launch(void* const* d_in, const int* in_sizes, int n_in,
                              void* d_out, int out_size) {
    const float* q = (const float*)d_in[0];
    const float* k = (const float*)d_in[1];
    const float* v = (const float*)d_in[2];
    const int*   w = (const int*)d_in[3];

    const int B = in_sizes[0] / (S_LEN * DIM);
    float* out = (float*)d_out;

    const int smem = 3 * BQ * DIM * (int)sizeof(float);   // 196608 B
    cudaFuncSetAttribute(swa_kernel, cudaFuncAttributeMaxDynamicSharedMemorySize, smem);

    dim3 grid(S_LEN / BQ, B);
    swa_kernel<<<grid, NTHREADS, smem>>>(q, k, v, w, out);
}

// round 2
// speedup vs baseline: 1.0026x; 1.0026x over previous
#include <cuda_runtime.h>
#include <cuda_bf16.h>
#include <math.h>

#define S_LEN 4096
#define DIM   128
#define BQ    128
#define BK    128
#define NTHREADS 256
#define NEG (-1000000000.0f)

// XOR swizzle on float4 index: rows differing by 8 land in different bank groups.
__device__ __forceinline__ int f4sw(int r, int f4) { return f4 ^ ((r >> 3) & 7); }

__global__ __launch_bounds__(NTHREADS, 1)
void swa_kernel(const float* __restrict__ gq, const float* __restrict__ gk,
                const float* __restrict__ gv, const int* __restrict__ wptr,
                float* __restrict__ gout)
{
    extern __shared__ float sm[];
    float* sQ  = sm;                 // [128][128] swizzled
    float* sKV = sm + BQ * DIM;      // K tile, then reused for V tile
    float* sP  = sm + 2 * BQ * DIM;  // probabilities

    const int tid = threadIdx.x;
    const int ty  = tid >> 4;        // 0..15 -> rows ty*8..ty*8+7
    const int tx  = tid & 15;        // 0..15 -> cols tx*8..tx*8+7
    const int q0  = blockIdx.x * BQ;
    const int b   = blockIdx.y;
    const int w   = *wptr;

    // ---- load Q tile (pre-scaled by 1/sqrt(D)) ----
    {
        const float scale = rsqrtf((float)DIM);
        const float4* qg = reinterpret_cast<const float4*>(gq + ((size_t)b * S_LEN + q0) * DIM);
        #pragma unroll
        for (int it = 0; it < (BQ * DIM / 4) / NTHREADS; it++) {
            int idx = tid + it * NTHREADS;
            int r = idx >> 5, f4 = idx & 31;
            float4 val = qg[idx];
            val.x *= scale; val.y *= scale; val.z *= scale; val.w *= scale;
            reinterpret_cast<float4*>(sQ + r * DIM)[f4sw(r, f4)] = val;
        }
    }

    float acc[8][8];
    float m_i[8], l_i[8];
    #pragma unroll
    for (int i = 0; i < 8; i++) {
        m_i[i] = -INFINITY; l_i[i] = 0.f;
        #pragma unroll
        for (int j = 0; j < 8; j++) acc[i][j] = 0.f;
    }

    int lo = q0 - (w - 1);            if (lo < 0) lo = 0;
    int hi = q0 + BQ - 1 + (w - 1);   if (hi > S_LEN - 1) hi = S_LEN - 1;

    const int keyA = ty & 7;
    const int keyB = tx & 7;

    for (int k0 = (lo & ~(BK - 1)); k0 <= hi; k0 += BK) {
        __syncthreads();   // prior PV done reading sKV (no-op first iter)

        // ---- load K tile ----
        {
            const float4* kg = reinterpret_cast<const float4*>(gk + ((size_t)b * S_LEN + k0) * DIM);
            #pragma unroll
            for (int it = 0; it < (BK * DIM / 4) / NTHREADS; it++) {
                int idx = tid + it * NTHREADS;
                int r = idx >> 5, f4 = idx & 31;
                reinterpret_cast<float4*>(sKV + r * DIM)[f4sw(r, f4)] = kg[idx];
            }
        }
        __syncthreads();   // Q + K visible

        // ---- S = Q K^T : 8x8 micro-tile per thread ----
        float c[8][8];
        #pragma unroll
        for (int i = 0; i < 8; i++)
            #pragma unroll
            for (int j = 0; j < 8; j++) c[i][j] = 0.f;

        #pragma unroll 2
        for (int d4 = 0; d4 < DIM / 4; d4++) {
            float4 a4[8];
            #pragma unroll
            for (int i = 0; i < 8; i++)
                a4[i] = reinterpret_cast<const float4*>(sQ + (ty * 8 + i) * DIM)[d4 ^ keyA];
            #pragma unroll
            for (int jh = 0; jh < 2; jh++) {
                float4 b4[4];
                #pragma unroll
                for (int j = 0; j < 4; j++)
                    b4[j] = reinterpret_cast<const float4*>(sKV + (tx * 8 + jh * 4 + j) * DIM)[d4 ^ keyB];
                #pragma unroll
                for (int i = 0; i < 8; i++)
                    #pragma unroll
                    for (int j = 0; j < 4; j++) {
                        c[i][jh * 4 + j] += a4[i].x * b4[j].x;
                        c[i][jh * 4 + j] += a4[i].y * b4[j].y;
                        c[i][jh * 4 + j] += a4[i].z * b4[j].z;
                        c[i][jh * 4 + j] += a4[i].w * b4[j].w;
                    }
            }
        }

        // ---- band mask + online softmax (registers + shfl over 16-lane row group) ----
        #pragma unroll
        for (int i = 0; i < 8; i++) {
            const int gi = q0 + ty * 8 + i;
            #pragma unroll
            for (int j = 0; j < 8; j++) {
                const int gj = k0 + tx * 8 + j;
                const int dd = gi - gj;
                if (dd >= w || -dd >= w) c[i][j] = NEG;
            }
            float mx = c[i][0];
            #pragma unroll
            for (int j = 1; j < 8; j++) mx = fmaxf(mx, c[i][j]);
            #pragma unroll
            for (int off = 8; off; off >>= 1)
                mx = fmaxf(mx, __shfl_xor_sync(0xffffffffu, mx, off, 16));

            const float mnew = fmaxf(m_i[i], mx);
            const float corr = __expf(m_i[i] - mnew);
            float sum = 0.f;
            #pragma unroll
            for (int j = 0; j < 8; j++) {
                float p = __expf(c[i][j] - mnew);
                c[i][j] = p;
                sum += p;
            }
            #pragma unroll
            for (int off = 8; off; off >>= 1)
                sum += __shfl_xor_sync(0xffffffffu, sum, off, 16);

            m_i[i] = mnew;
            l_i[i] = l_i[i] * corr + sum;
            #pragma unroll
            for (int j = 0; j < 8; j++) acc[i][j] *= corr;
        }

        __syncthreads();   // everyone done reading K before V overwrites sKV

        // ---- store P to smem, load V tile into sKV ----
        #pragma unroll
        for (int i = 0; i < 8; i++) {
            int r = ty * 8 + i;
            float4 p0 = make_float4(c[i][0], c[i][1], c[i][2], c[i][3]);
            float4 p1 = make_float4(c[i][4], c[i][5], c[i][6], c[i][7]);
            reinterpret_cast<float4*>(sP + r * DIM)[f4sw(r, tx * 2)]     = p0;
            reinterpret_cast<float4*>(sP + r * DIM)[f4sw(r, tx * 2 + 1)] = p1;
        }
        {
            const float4* vg = reinterpret_cast<const float4*>(gv + ((size_t)b * S_LEN + k0) * DIM);
            #pragma unroll
            for (int it = 0; it < (BK * DIM / 4) / NTHREADS; it++) {
                int idx = tid + it * NTHREADS;
                int r = idx >> 5, f4 = idx & 31;
                reinterpret_cast<float4*>(sKV + r * DIM)[f4sw(r, f4)] = vg[idx];
            }
        }
        __syncthreads();   // P + V visible

        // ---- O += P V : 8 rows x 8 cols per thread ----
        #pragma unroll 2
        for (int kk = 0; kk < BK; kk++) {
            const int pidx = (((kk >> 2) ^ keyA) << 2) | (kk & 3);
            float pv[8];
            #pragma unroll
            for (int i = 0; i < 8; i++)
                pv[i] = sP[(ty * 8 + i) * DIM + pidx];
            const int keyV = (kk >> 3) & 7;
            const float4 v0 = reinterpret_cast<const float4*>(sKV + kk * DIM)[(tx * 2) ^ keyV];
            const float4 v1 = reinterpret_cast<const float4*>(sKV + kk * DIM)[(tx * 2 + 1) ^ keyV];
            #pragma unroll
            for (int i = 0; i < 8; i++) {
                acc[i][0] += pv[i] * v0.x;  acc[i][1] += pv[i] * v0.y;
                acc[i][2] += pv[i] * v0.z;  acc[i][3] += pv[i] * v0.w;
                acc[i][4] += pv[i] * v1.x;  acc[i][5] += pv[i] * v1.y;
                acc[i][6] += pv[i] * v1.z;  acc[i][7] += pv[i] * v1.w;
            }
        }
    }

    // ---- normalize + store ----
    float4* og = reinterpret_cast<float4*>(gout + ((size_t)b * S_LEN + q0) * DIM);
    #pragma unroll
    for (int i = 0; i < 8; i++) {
        const float inv = 1.0f / l_i[i];
        float4 o0 = make_float4(acc[i][0] * inv, acc[i][1] * inv, acc[i][2] * inv, acc[i][3] * inv);
        float4 o1 = make_float4(acc[i][4] * inv, acc[i][5] * inv, acc[i][6] * inv, acc[i][7] * inv);
        og[(ty * 8 + i) * (DIM / 4) + tx * 2]     = o0;
        og[(ty * 8 + i) * (DIM / 4) + tx * 2 + 1] = o1;
    }
}

extern "C" void kernel_launch(void* const* d_in, const int* in_sizes, int n_in,
                              void* d_out, int out_size) {
    const float* q = (const float*)d_in[0];
    const float* k = (const float*)d_in[1];
    const float* v = (const float*)d_in[2];
    const int*   w = (const int*)d_in[3];

    const int B = in_sizes[0] / (S_LEN * DIM);
    float* out = (float*)d_out;

    const int smem = 3 * BQ * DIM * (int)sizeof(float);   // 196608 B
    cudaFuncSetAttribute(swa_kernel, cudaFuncAttributeMaxDynamicSharedMemorySize, smem);

    dim3 grid(S_LEN / BQ, B);
    swa_kernel<<<grid, NTHREADS, smem>>>(q, k, v, w, out);
}

// round 4
// speedup vs baseline: 2.3269x; 2.3208x over previous
#include <cuda_runtime.h>
#include <cuda_bf16.h>
#include <cstdint>
#include <math.h>

#define S_LEN 4096
#define DIM   128
#define BQ    128
#define BK    128
#define NT    256

// smem byte offsets (bf16 tiles: 128 rows x 256B, chunk-swizzled)
#define OQH 0
#define OQL 32768
#define OKH 65536
#define OKL 98304
#define OVH 131072
#define OVL 163840
#define OSTG 65536            // f32 output staging (stride 140 floats), reuses K region
#define SMEM_BYTES 196608

__device__ __forceinline__ uint32_t s2u(const void* p) {
    uint32_t a;
    asm("{ .reg .u64 t; cvta.to.shared.u64 t, %1; cvt.u32.u64 %0, t; }" : "=r"(a) : "l"(p));
    return a;
}

__device__ __forceinline__ void ldm4(uint32_t a, uint32_t& r0, uint32_t& r1, uint32_t& r2, uint32_t& r3) {
    asm volatile("ldmatrix.sync.aligned.m8n8.x4.shared.b16 {%0,%1,%2,%3}, [%4];"
                 : "=r"(r0), "=r"(r1), "=r"(r2), "=r"(r3) : "r"(a));
}
__device__ __forceinline__ void ldm4t(uint32_t a, uint32_t& r0, uint32_t& r1, uint32_t& r2, uint32_t& r3) {
    asm volatile("ldmatrix.sync.aligned.m8n8.x4.trans.shared.b16 {%0,%1,%2,%3}, [%4];"
                 : "=r"(r0), "=r"(r1), "=r"(r2), "=r"(r3) : "r"(a));
}
__device__ __forceinline__ void mma_bf16(float* c, const uint32_t* a, uint32_t b0, uint32_t b1) {
    asm volatile("mma.sync.aligned.m16n8k16.row.col.f32.bf16.bf16.f32 "
                 "{%0,%1,%2,%3}, {%4,%5,%6,%7}, {%8,%9}, {%0,%1,%2,%3};"
                 : "+f"(c[0]), "+f"(c[1]), "+f"(c[2]), "+f"(c[3])
                 : "r"(a[0]), "r"(a[1]), "r"(a[2]), "r"(a[3]), "r"(b0), "r"(b1));
}

// split pair of fp32 into bf16 hi/lo packed b32 (element0 in low half)
__device__ __forceinline__ void split2(float x, float y, uint32_t& hi, uint32_t& lo) {
    __nv_bfloat162 h = __floats2bfloat162_rn(x, y);
    float rx = x - __bfloat162float(h.x);
    float ry = y - __bfloat162float(h.y);
    __nv_bfloat162 l = __floats2bfloat162_rn(rx, ry);
    hi = *reinterpret_cast<uint32_t*>(&h);
    lo = *reinterpret_cast<uint32_t*>(&l);
}

// fp32 [128][128] tile -> bf16 hi/lo swizzled smem tiles
__device__ __forceinline__ void load_conv(const float4* __restrict__ g, char* smc,
                                          int offH, int offL, int tid, float scale) {
    #pragma unroll
    for (int i = 0; i < 16; i++) {
        int idx = tid + i * NT;
        int row = idx >> 5, c4 = idx & 31;
        int chunk = c4 >> 1, sub = (c4 & 1) << 3;
        float4 vv = g[idx];
        uint32_t h0, l0, h1, l1;
        split2(vv.x * scale, vv.y * scale, h0, l0);
        split2(vv.z * scale, vv.w * scale, h1, l1);
        int off = row * 256 + ((chunk ^ (row & 7)) << 4) + sub;
        *reinterpret_cast<uint2*>(smc + offH + off) = make_uint2(h0, h1);
        *reinterpret_cast<uint2*>(smc + offL + off) = make_uint2(l0, l1);
    }
}

__global__ __launch_bounds__(NT, 1)
void swa_mma_kernel(const float* __restrict__ gq, const float* __restrict__ gk,
                    const float* __restrict__ gv, const int* __restrict__ wptr,
                    float* __restrict__ gout)
{
    extern __shared__ char smc[];
    const uint32_t sb = s2u(smc);
    const int tid = threadIdx.x, lane = tid & 31, wr = tid >> 5;
    const int q0 = blockIdx.x * BQ, b = blockIdx.y;
    const int w = wptr[0];
    const float scale = rsqrtf((float)DIM);

    const int il0 = wr * 16 + (lane >> 2);      // this thread's low output row (tile-local)
    const int hi4 = lane >> 4;                  // 0/1
    const int lo7 = lane & 7;
    const int cbl = (lane >> 3) & 1;
    const int rbl = (lane & 7) + ((lane >> 4) << 3);

    load_conv(reinterpret_cast<const float4*>(gq + ((size_t)b * S_LEN + q0) * DIM),
              smc, OQH, OQL, tid, scale);

    int lo = q0 - (w - 1);              if (lo < 0) lo = 0;
    int hi = q0 + BQ - 1 + (w - 1);     if (hi > S_LEN - 1) hi = S_LEN - 1;
    const int t0 = lo >> 7, t1 = hi >> 7;

    float o[16][4];
    #pragma unroll
    for (int n = 0; n < 16; n++)
        #pragma unroll
        for (int e = 0; e < 4; e++) o[n][e] = 0.f;
    float rs0 = 0.f, rs1 = 0.f;

    for (int t = t0; t <= t1; t++) {
        __syncthreads();                        // Q ready (1st) / prev tile compute done
        const int k0 = t << 7;
        load_conv(reinterpret_cast<const float4*>(gk + ((size_t)b * S_LEN + k0) * DIM),
                  smc, OKH, OKL, tid, 1.f);
        load_conv(reinterpret_cast<const float4*>(gv + ((size_t)b * S_LEN + k0) * DIM),
                  smc, OVH, OVL, tid, 1.f);
        __syncthreads();

        const int dqk = q0 - k0;
        const int adq = dqk < 0 ? -dqk : dqk;
        const bool needMask = (adq + 127) >= w;
        int npLo = 0, npHi = 7, kkLo = 0, kkHi = 7;
        if (w == BK) {
            if (dqk > 0)      { npLo = wr; kkLo = wr; }   // keys before queries
            else if (dqk < 0) { npHi = wr; kkHi = wr; }   // keys after queries
        }

        // ================= S = Q K^T (bf16x3: HH, HL, LH) =================
        float c[16][4];
        #pragma unroll
        for (int n = 0; n < 16; n++)
            #pragma unroll
            for (int e = 0; e < 4; e++) c[n][e] = 0.f;

        uint32_t A[8][4];
        #pragma unroll
        for (int pass = 0; pass < 3; pass++) {
            if (pass != 1) {
                uint32_t qb = sb + (pass ? OQL : OQH)
                            + (uint32_t)((wr * 16 + (lane & 15)) * 256);
                #pragma unroll
                for (int kk = 0; kk < 8; kk++)
                    ldm4(qb + (uint32_t)((((2 * kk + hi4) ^ lo7)) << 4),
                         A[kk][0], A[kk][1], A[kk][2], A[kk][3]);
            }
            const uint32_t kb = sb + ((pass == 1) ? OKL : OKH);
            #pragma unroll
            for (int kk = 0; kk < 8; kk++) {
                #pragma unroll
                for (int np = 0; np < 8; np++) {
                    if (np >= npLo && np <= npHi) {
                        uint32_t addr = kb + (uint32_t)((np * 16 + rbl) * 256
                                      + (((2 * kk + cbl) ^ lo7) << 4));
                        uint32_t b0, b1, b2, b3;
                        ldm4(addr, b0, b1, b2, b3);
                        mma_bf16(c[2 * np],     A[kk], b0, b1);
                        mma_bf16(c[2 * np + 1], A[kk], b2, b3);
                    }
                }
            }
        }

        // ================= mask + exp + rowsum =================
        float ps0 = 0.f, ps1 = 0.f;
        if (needMask) {
            #pragma unroll
            for (int n = 0; n < 16; n++) {
                int jg = k0 + n * 8 + ((lane & 3) << 1);
                int d0 = (q0 + il0) - jg;
                float e;
                e = (d0 < w && d0 > -w)         ? __expf(c[n][0]) : 0.f; c[n][0] = e; ps0 += e;
                e = (d0 - 1 < w && d0 - 1 > -w) ? __expf(c[n][1]) : 0.f; c[n][1] = e; ps0 += e;
                e = (d0 + 8 < w && d0 + 8 > -w) ? __expf(c[n][2]) : 0.f; c[n][2] = e; ps1 += e;
                e = (d0 + 7 < w && d0 + 7 > -w) ? __expf(c[n][3]) : 0.f; c[n][3] = e; ps1 += e;
            }
        } else {
            #pragma unroll
            for (int n = 0; n < 16; n++) {
                float e0 = __expf(c[n][0]), e1 = __expf(c[n][1]);
                float e2 = __expf(c[n][2]), e3 = __expf(c[n][3]);
                c[n][0] = e0; c[n][1] = e1; c[n][2] = e2; c[n][3] = e3;
                ps0 += e0 + e1; ps1 += e2 + e3;
            }
        }
        ps0 += __shfl_xor_sync(0xffffffffu, ps0, 1);
        ps0 += __shfl_xor_sync(0xffffffffu, ps0, 2);
        ps1 += __shfl_xor_sync(0xffffffffu, ps1, 1);
        ps1 += __shfl_xor_sync(0xffffffffu, ps1, 2);
        rs0 += ps0; rs1 += ps1;

        // ================= P -> bf16 hi/lo A-fragments (registers only) =================
        uint32_t ph[8][4], pl[8][4];
        #pragma unroll
        for (int kk = 0; kk < 8; kk++) {
            split2(c[2 * kk][0],     c[2 * kk][1],     ph[kk][0], pl[kk][0]);
            split2(c[2 * kk][2],     c[2 * kk][3],     ph[kk][1], pl[kk][1]);
            split2(c[2 * kk + 1][0], c[2 * kk + 1][1], ph[kk][2], pl[kk][2]);
            split2(c[2 * kk + 1][2], c[2 * kk + 1][3], ph[kk][3], pl[kk][3]);
        }

        // ================= O += P V (bf16x3) =================
        #pragma unroll
        for (int pass = 0; pass < 3; pass++) {
            const uint32_t vb = sb + ((pass == 1) ? OVL : OVH);
            #pragma unroll
            for (int kk = 0; kk < 8; kk++) {
                if (kk >= kkLo && kk <= kkHi) {
                    const uint32_t* Af = (pass == 2) ? pl[kk] : ph[kk];
                    uint32_t rowoff = vb + (uint32_t)((kk * 16 + (lane & 15)) * 256);
                    #pragma unroll
                    for (int vp = 0; vp < 8; vp++) {
                        uint32_t addr = rowoff + (uint32_t)((((2 * vp + hi4) ^ lo7)) << 4);
                        uint32_t b0, b1, b2, b3;
                        ldm4t(addr, b0, b1, b2, b3);
                        mma_bf16(o[2 * vp],     Af, b0, b1);
                        mma_bf16(o[2 * vp + 1], Af, b2, b3);
                    }
                }
            }
        }
    }

    // ================= normalize, stage in smem, coalesced store =================
    __syncthreads();                 // all warps done reading K/V regions
    const float inv0 = 1.0f / rs0, inv1 = 1.0f / rs1;
    float* stg = reinterpret_cast<float*>(smc + OSTG);   // stride 140 floats
    const int jd = (lane & 3) << 1;
    #pragma unroll
    for (int nd = 0; nd < 16; nd++) {
        int col = nd * 8 + jd;
        *reinterpret_cast<float2*>(&stg[il0 * 140 + col]) =
            make_float2(o[nd][0] * inv0, o[nd][1] * inv0);
        *reinterpret_cast<float2*>(&stg[(il0 + 8) * 140 + col]) =
            make_float2(o[nd][2] * inv1, o[nd][3] * inv1);
    }
    __syncthreads();
    float4* og = reinterpret_cast<float4*>(gout + ((size_t)b * S_LEN + q0) * DIM);
    #pragma unroll
    for (int i = 0; i < 16; i++) {
        int idx = tid + i * NT;
        int row = idx >> 5, c4 = idx & 31;
        og[idx] = *reinterpret_cast<float4*>(&stg[row * 140 + c4 * 4]);
    }
}

extern "C" void kernel_launch(void* const* d_in, const int* in_sizes, int n_in,
                              void* d_out, int out_size) {
    const float* q = (const float*)d_in[0];
    const float* k = (const float*)d_in[1];
    const float* v = (const float*)d_in[2];
    const int*   w = (const int*)d_in[3];
    const int B = in_sizes[0] / (S_LEN * DIM);
    float* out = (float*)d_out;

    cudaFuncSetAttribute(swa_mma_kernel, cudaFuncAttributeMaxDynamicSharedMemorySize, SMEM_BYTES);
    dim3 grid(S_LEN / BQ, B);
    swa_mma_kernel<<<grid, NT, SMEM_BYTES>>>(q, k, v, w, out);
}

// round 5
// speedup vs baseline: 2.5981x; 1.1165x over previous
#include <cuda_runtime.h>
#include <cuda_bf16.h>
#include <cstdint>
#include <math.h>

#define S_LEN 4096
#define DIM   128
#define BQ    64
#define BK    64
#define NT    256

// per-CTA smem byte offsets (64-row tiles, 256B/row bf16 except P: 128B/row)
#define OQH 0
#define OQL 16384
#define OKH 32768
#define OKL 49152
#define OVH 65536
#define OVL 81920
#define OPH 98304
#define OPL 106496
#define SMEM_BYTES 114688
// end-of-kernel reuse of dead K region:
#define ORS OKH               // rowsum combine: 2 x 64 floats
#define OSTG (OKH + 1024)     // f32 staging, stride 132 floats

__device__ __forceinline__ uint32_t s2u(const void* p) {
    uint32_t a;
    asm("{ .reg .u64 t; cvta.to.shared.u64 t, %1; cvt.u32.u64 %0, t; }" : "=r"(a) : "l"(p));
    return a;
}
__device__ __forceinline__ void ldm4(uint32_t a, uint32_t& r0, uint32_t& r1, uint32_t& r2, uint32_t& r3) {
    asm volatile("ldmatrix.sync.aligned.m8n8.x4.shared.b16 {%0,%1,%2,%3}, [%4];"
                 : "=r"(r0), "=r"(r1), "=r"(r2), "=r"(r3) : "r"(a));
}
__device__ __forceinline__ void ldm4t(uint32_t a, uint32_t& r0, uint32_t& r1, uint32_t& r2, uint32_t& r3) {
    asm volatile("ldmatrix.sync.aligned.m8n8.x4.trans.shared.b16 {%0,%1,%2,%3}, [%4];"
                 : "=r"(r0), "=r"(r1), "=r"(r2), "=r"(r3) : "r"(a));
}
__device__ __forceinline__ void mma_bf16(float* c, const uint32_t* a, uint32_t b0, uint32_t b1) {
    asm volatile("mma.sync.aligned.m16n8k16.row.col.f32.bf16.bf16.f32 "
                 "{%0,%1,%2,%3}, {%4,%5,%6,%7}, {%8,%9}, {%0,%1,%2,%3};"
                 : "+f"(c[0]), "+f"(c[1]), "+f"(c[2]), "+f"(c[3])
                 : "r"(a[0]), "r"(a[1]), "r"(a[2]), "r"(a[3]), "r"(b0), "r"(b1));
}
__device__ __forceinline__ void split2(float x, float y, uint32_t& hi, uint32_t& lo) {
    __nv_bfloat162 h = __floats2bfloat162_rn(x, y);
    float rx = x - __bfloat162float(h.x);
    float ry = y - __bfloat162float(h.y);
    __nv_bfloat162 l = __floats2bfloat162_rn(rx, ry);
    hi = *reinterpret_cast<uint32_t*>(&h);
    lo = *reinterpret_cast<uint32_t*>(&l);
}

// fp32 [64][128] tile -> bf16 hi/lo chunk-swizzled smem (256B rows)
__device__ __forceinline__ void load_conv64(const float4* __restrict__ g, char* smc,
                                            int offH, int offL, int tid, float scale) {
    #pragma unroll
    for (int i = 0; i < 8; i++) {
        int idx = tid + i * NT;
        int row = idx >> 5, c4 = idx & 31;
        int chunk = c4 >> 1, sub = (c4 & 1) << 3;
        float4 vv = g[idx];
        uint32_t h0, l0, h1, l1;
        split2(vv.x * scale, vv.y * scale, h0, l0);
        split2(vv.z * scale, vv.w * scale, h1, l1);
        int off = row * 256 + ((chunk ^ (row & 7)) << 4) + sub;
        *reinterpret_cast<uint2*>(smc + offH + off) = make_uint2(h0, h1);
        *reinterpret_cast<uint2*>(smc + offL + off) = make_uint2(l0, l1);
    }
}

__global__ __launch_bounds__(NT, 2)
void swa_mma_kernel(const float* __restrict__ gq, const float* __restrict__ gk,
                    const float* __restrict__ gv, const int* __restrict__ wptr,
                    float* __restrict__ gout)
{
    extern __shared__ char smc[];
    const uint32_t sb = s2u(smc);
    const int tid = threadIdx.x, lane = tid & 31, wr = tid >> 5;
    const int rg = wr & 3;            // row group: rows rg*16..+15
    const int nh = wr >> 2;           // key-half (QK) / output-col-half (PV)
    const int q0 = blockIdx.x * BQ, b = blockIdx.y;
    const int w = wptr[0];
    const float scale = rsqrtf((float)DIM);

    const int il0 = rg * 16 + (lane >> 2);    // low output row (tile-local)
    const int gr  = q0 + il0;
    const int hi4 = lane >> 4;
    const int lo7 = lane & 7;
    const int cbl = (lane >> 3) & 1;
    const int rbl = (lane & 7) + ((lane >> 4) << 3);

    load_conv64(reinterpret_cast<const float4*>(gq + ((size_t)b * S_LEN + q0) * DIM),
                smc, OQH, OQL, tid, scale);

    int lo = q0 - (w - 1);              if (lo < 0) lo = 0;
    int hi = q0 + BQ - 1 + (w - 1);     if (hi > S_LEN - 1) hi = S_LEN - 1;
    const int t0 = lo >> 6, t1 = hi >> 6;

    float o[8][4];
    #pragma unroll
    for (int n = 0; n < 8; n++)
        #pragma unroll
        for (int e = 0; e < 4; e++) o[n][e] = 0.f;
    float rs0 = 0.f, rs1 = 0.f;

    for (int t = t0; t <= t1; t++) {
        __syncthreads();                     // prev tile fully consumed
        const int k0 = t << 6;
        load_conv64(reinterpret_cast<const float4*>(gk + ((size_t)b * S_LEN + k0) * DIM),
                    smc, OKH, OKL, tid, 1.f);
        load_conv64(reinterpret_cast<const float4*>(gv + ((size_t)b * S_LEN + k0) * DIM),
                    smc, OVH, OVL, tid, 1.f);
        __syncthreads();

        // chunk-skip predicates (uniform per warp)
        const int rlo = q0 + rg * 16, rhi = rlo + 15;
        bool skq[2], skp[4];
        #pragma unroll
        for (int np2 = 0; np2 < 2; np2++) {
            int kb0 = k0 + nh * 32 + np2 * 16;
            skq[np2] = (kb0 - rhi >= w) || (rlo - (kb0 + 15) >= w);
        }
        #pragma unroll
        for (int kk2 = 0; kk2 < 4; kk2++) {
            int kb0 = k0 + kk2 * 16;
            skp[kk2] = (kb0 - rhi >= w) || (rlo - (kb0 + 15) >= w);
        }

        // ================= S = Q K^T (bf16x3) =================
        float c[4][4];
        #pragma unroll
        for (int n = 0; n < 4; n++)
            #pragma unroll
            for (int e = 0; e < 4; e++) c[n][e] = 0.f;

        uint32_t A[8][4];
        #pragma unroll
        for (int pass = 0; pass < 3; pass++) {
            if (pass != 1) {
                uint32_t qb = sb + (pass ? OQL : OQH)
                            + (uint32_t)((rg * 16 + (lane & 15)) * 256);
                #pragma unroll
                for (int kk = 0; kk < 8; kk++)
                    ldm4(qb + (uint32_t)(((2 * kk + hi4) ^ lo7) << 4),
                         A[kk][0], A[kk][1], A[kk][2], A[kk][3]);
            }
            const uint32_t kb = sb + ((pass == 1) ? OKL : OKH);
            #pragma unroll
            for (int kk = 0; kk < 8; kk++) {
                #pragma unroll
                for (int np2 = 0; np2 < 2; np2++) {
                    if (!skq[np2]) {
                        uint32_t addr = kb + (uint32_t)(((nh * 2 + np2) * 16 + rbl) * 256
                                      + (((2 * kk + cbl) ^ lo7) << 4));
                        uint32_t b0, b1, b2, b3;
                        ldm4(addr, b0, b1, b2, b3);
                        mma_bf16(c[np2 * 2],     A[kk], b0, b1);
                        mma_bf16(c[np2 * 2 + 1], A[kk], b2, b3);
                    }
                }
            }
        }

        // ================= mask + exp + partial rowsum =================
        float ps0 = 0.f, ps1 = 0.f;
        #pragma unroll
        for (int j = 0; j < 4; j++) {
            int jg = k0 + nh * 32 + j * 8 + ((lane & 3) << 1);
            int d0 = gr - jg;
            float e;
            e = (d0 < w && d0 > -w)         ? __expf(c[j][0]) : 0.f; c[j][0] = e; ps0 += e;
            e = (d0 - 1 < w && d0 - 1 > -w) ? __expf(c[j][1]) : 0.f; c[j][1] = e; ps0 += e;
            e = (d0 + 8 < w && d0 + 8 > -w) ? __expf(c[j][2]) : 0.f; c[j][2] = e; ps1 += e;
            e = (d0 + 7 < w && d0 + 7 > -w) ? __expf(c[j][3]) : 0.f; c[j][3] = e; ps1 += e;
        }
        ps0 += __shfl_xor_sync(0xffffffffu, ps0, 1);
        ps0 += __shfl_xor_sync(0xffffffffu, ps0, 2);
        ps1 += __shfl_xor_sync(0xffffffffu, ps1, 1);
        ps1 += __shfl_xor_sync(0xffffffffu, ps1, 2);
        rs0 += ps0; rs1 += ps1;

        // ================= P -> smem (bf16 hi/lo, ldmatrix-ready swizzle) =================
        #pragma unroll
        for (int j = 0; j < 4; j++) {
            uint32_t h, l;
            int off0 = il0 * 128 + (((nh * 4 + j) ^ (il0 & 7)) << 4) + ((lane & 3) << 2);
            split2(c[j][0], c[j][1], h, l);
            *reinterpret_cast<uint32_t*>(smc + OPH + off0) = h;
            *reinterpret_cast<uint32_t*>(smc + OPL + off0) = l;
            int r1 = il0 + 8;
            int off1 = r1 * 128 + (((nh * 4 + j) ^ (r1 & 7)) << 4) + ((lane & 3) << 2);
            split2(c[j][2], c[j][3], h, l);
            *reinterpret_cast<uint32_t*>(smc + OPH + off1) = h;
            *reinterpret_cast<uint32_t*>(smc + OPL + off1) = l;
        }
        __syncthreads();                     // P visible to partner warps

        // ================= O += P V (bf16x3) =================
        #pragma unroll
        for (int pass = 0; pass < 3; pass++) {
            const uint32_t pb = sb + ((pass == 2) ? OPL : OPH);
            const uint32_t vb = sb + ((pass == 1) ? OVL : OVH);
            #pragma unroll
            for (int kk2 = 0; kk2 < 4; kk2++) {
                if (!skp[kk2]) {
                    uint32_t a0, a1, a2, a3;
                    ldm4(pb + (uint32_t)((rg * 16 + (lane & 15)) * 128
                             + (((2 * kk2 + hi4) ^ lo7) << 4)), a0, a1, a2, a3);
                    uint32_t Af[4] = {a0, a1, a2, a3};
                    uint32_t vrow = vb + (uint32_t)((kk2 * 16 + (lane & 15)) * 256);
                    #pragma unroll
                    for (int vp2 = 0; vp2 < 4; vp2++) {
                        uint32_t b0, b1, b2, b3;
                        ldm4t(vrow + (uint32_t)(((nh * 8 + 2 * vp2 + hi4) ^ lo7) << 4),
                              b0, b1, b2, b3);
                        mma_bf16(o[vp2 * 2],     Af, b0, b1);
                        mma_bf16(o[vp2 * 2 + 1], Af, b2, b3);
                    }
                }
            }
        }
    }

    // ================= rowsum combine + normalize + store =================
    __syncthreads();                         // K/V/P dead
    float* rsb = reinterpret_cast<float*>(smc + ORS);
    if ((lane & 3) == 0) {
        rsb[nh * 64 + il0]     = rs0;
        rsb[nh * 64 + il0 + 8] = rs1;
    }
    __syncthreads();
    const float inv0 = 1.0f / (rsb[il0]     + rsb[64 + il0]);
    const float inv1 = 1.0f / (rsb[il0 + 8] + rsb[64 + il0 + 8]);

    float* stg = reinterpret_cast<float*>(smc + OSTG);    // stride 132
    const int jd = (lane & 3) << 1;
    #pragma unroll
    for (int n = 0; n < 8; n++) {
        int col = nh * 64 + n * 8 + jd;
        *reinterpret_cast<float2*>(&stg[il0 * 132 + col]) =
            make_float2(o[n][0] * inv0, o[n][1] * inv0);
        *reinterpret_cast<float2*>(&stg[(il0 + 8) * 132 + col]) =
            make_float2(o[n][2] * inv1, o[n][3] * inv1);
    }
    __syncthreads();
    float4* og = reinterpret_cast<float4*>(gout + ((size_t)b * S_LEN + q0) * DIM);
    #pragma unroll
    for (int i = 0; i < 8; i++) {
        int idx = tid + i * NT;
        int row = idx >> 5, c4 = idx & 31;
        og[idx] = *reinterpret_cast<float4*>(&stg[row * 132 + c4 * 4]);
    }
}

extern "C" void kernel_launch(void* const* d_in, const int* in_sizes, int n_in,
                              void* d_out, int out_size) {
    const float* q = (const float*)d_in[0];
    const float* k = (const float*)d_in[1];
    const float* v = (const float*)d_in[2];
    const int*   w = (const int*)d_in[3];
    const int B = in_sizes[0] / (S_LEN * DIM);
    float* out = (float*)d_out;

    cudaFuncSetAttribute(swa_mma_kernel, cudaFuncAttributeMaxDynamicSharedMemorySize, SMEM_BYTES);
    dim3 grid(S_LEN / BQ, B);
    swa_mma_kernel<<<grid, NT, SMEM_BYTES>>>(q, k, v, w, out);
}